// round 11
// baseline (speedup 1.0000x reference)
#include <cuda_runtime.h>
#include <cuda_bf16.h>
#include <math.h>

#define BB 32
#define NN 64
#define DD 64
typedef unsigned long long U64;
typedef unsigned int U32;

// Scratch (no allocations allowed)
__device__ float g_keys[4 * BB * NN * DD];   // 4 key matrices per batch
__device__ float g_att[6 * BB * NN * NN];    // 6 att matrices (pre-scaled by scale/2)
__device__ float g_M[BB * NN * 6];           // per (b,i): sum_l dl dl^T (6 unique)
__device__ float g_agg[BB * NN];

// ---- packed f32x2 helpers (FFMA2 only reachable via PTX) ----
__device__ __forceinline__ U64 pk2(float a, float b) {
    U64 r; asm("mov.b64 %0,{%1,%2};" : "=l"(r) : "f"(a), "f"(b)); return r;
}
__device__ __forceinline__ void upk2(U64 v, float& a, float& b) {
    asm("mov.b64 {%0,%1},%2;" : "=f"(a), "=f"(b) : "l"(v));
}
__device__ __forceinline__ U64 mul2(U64 a, U64 b) {
    U64 d; asm("mul.rn.f32x2 %0,%1,%2;" : "=l"(d) : "l"(a), "l"(b)); return d;
}
__device__ __forceinline__ U64 fma2(U64 a, U64 b, U64 c) {
    U64 d; asm("fma.rn.f32x2 %0,%1,%2,%3;" : "=l"(d) : "l"(a), "l"(b), "l"(c)); return d;
}
// ---- bf16x2 helpers ----
__device__ __forceinline__ U32 haddbf2(U32 a, U32 b) {
    U32 d; asm("add.rn.bf16x2 %0,%1,%2;" : "=r"(d) : "r"(a), "r"(b)); return d;
}
__device__ __forceinline__ U32 tanhbf2(U32 a) {
    U32 d; asm("tanh.approx.bf16x2 %0,%1;" : "=r"(d) : "r"(a)); return d;
}
__device__ __forceinline__ U32 cvt2bf2(float a, float b) {
    U32 d; asm("cvt.rn.bf16x2.f32 %0,%1,%2;" : "=r"(d) : "f"(a), "f"(b)); return d;
}
// bf16x2 -> packed f32x2 pair: lo<<16, hi&0xffff0000 (ALU only)
__device__ __forceinline__ U64 bf2_to_f32x2(U32 t) {
    return pk2(__uint_as_float(t << 16), __uint_as_float(t & 0xffff0000u));
}

// ---------------------------------------------------------------------------
// Keys: 3->64 dense for the 4 projections, to gmem. grid (4, 32), 256 thr.
// ---------------------------------------------------------------------------
__global__ void keys_kernel(const float* __restrict__ pc,
                            const float* __restrict__ Wq,  const float* __restrict__ bq,
                            const float* __restrict__ Wk1, const float* __restrict__ bk1,
                            const float* __restrict__ Wk2, const float* __restrict__ bk2,
                            const float* __restrict__ Wk3, const float* __restrict__ bk3)
{
    const int m = blockIdx.x, b = blockIdx.y, tid = threadIdx.x;
    const float* Ws[4] = {Wq, Wk1, Wk2, Wk3};
    const float* bs[4] = {bq, bk1, bk2, bk3};
    const float* W = Ws[m]; const float* bias = bs[m];
    const float* pcb = pc + b * NN * 3;
    float* out = g_keys + (m * BB + b) * NN * DD;
    for (int idx = tid; idx < NN * DD; idx += blockDim.x) {
        int n = idx >> 6, d = idx & 63;
        float p0 = pcb[n * 3], p1 = pcb[n * 3 + 1], p2 = pcb[n * 3 + 2];
        out[idx] = fmaf(p0, W[d], fmaf(p1, W[DD + d], fmaf(p2, W[2 * DD + d], bias[d])));
    }
}

// ---------------------------------------------------------------------------
// Atts: 64x64 dot matrices, pre-scaled by scale/2 = 0.0625 (tanh half-arg).
// m: 0 ajk[j][k], 1 ajl[j][l], 2 akl[k][l] (k-major!), 3 aqj[i][j],
//    4 aqk[i][k], 5 aql[i][l].  grid (6, 32), 256 thr.
// ---------------------------------------------------------------------------
__global__ void att_kernel()
{
    __shared__ float L[NN * 65];
    __shared__ float R[NN * 65];
    const int m = blockIdx.x, b = blockIdx.y, tid = threadIdx.x;
    const int lsel[6] = {1, 1, 2, 0, 0, 0};
    const int rsel[6] = {2, 3, 3, 1, 2, 3};
    const float* gl = g_keys + (lsel[m] * BB + b) * NN * DD;
    const float* gr = g_keys + (rsel[m] * BB + b) * NN * DD;
    for (int idx = tid; idx < NN * DD; idx += blockDim.x) {
        int n = idx >> 6, d = idx & 63;
        L[n * 65 + d] = gl[idx];
        R[n * 65 + d] = gr[idx];
    }
    __syncthreads();
    const float SC = 0.0625f;  // (1/sqrt(64)) / 2
    float* outm = g_att + (m * BB + b) * NN * NN;
    for (int idx = tid; idx < NN * NN; idx += blockDim.x) {
        int r = idx >> 6, c = idx & 63;
        float s = 0.f;
        #pragma unroll 8
        for (int d = 0; d < DD; ++d) s = fmaf(L[r * 65 + d], R[c * 65 + d], s);
        outm[idx] = SC * s;
    }
}

// ---------------------------------------------------------------------------
// M matrices: per (b,i), M = sum_l (p_l - p_i)(p_l - p_i)^T. grid 32, 64 thr.
// ---------------------------------------------------------------------------
__global__ void mmat_kernel(const float* __restrict__ pc)
{
    __shared__ float px[NN], py[NN], pz[NN];
    const int b = blockIdx.x, t = threadIdx.x;
    px[t] = pc[(b * NN + t) * 3 + 0];
    py[t] = pc[(b * NN + t) * 3 + 1];
    pz[t] = pc[(b * NN + t) * 3 + 2];
    __syncthreads();
    float pix = px[t], piy = py[t], piz = pz[t];
    float xx = 0, xy = 0, xz = 0, yy = 0, yz = 0, zz = 0;
    #pragma unroll 4
    for (int l = 0; l < NN; ++l) {
        float dx = px[l] - pix, dy = py[l] - piy, dz = pz[l] - piz;
        xx = fmaf(dx, dx, xx); xy = fmaf(dx, dy, xy); xz = fmaf(dx, dz, xz);
        yy = fmaf(dy, dy, yy); yz = fmaf(dy, dz, yz); zz = fmaf(dz, dz, zz);
    }
    float* o = g_M + (b * NN + t) * 6;
    o[0] = xx; o[1] = xy; o[2] = xz; o[3] = yy; o[4] = yz; o[5] = zz;
}

// ---------------------------------------------------------------------------
// Main: one block per (b,i). 256 thr: k = tid&63, jb = tid>>6 (16 j each).
// Energies (bjl, alk) live in smem as bf16; energy sum in bf16x2 (HADD2),
// gate via ONE tanh.approx.bf16x2 per 2 elements (halves MUFU), unpacked to
// f32x2 with ALU-only shifts. det chain + accumulation stay f32x2 exact.
// det^2 half-sum folded analytically per thread (A:Q contraction).
// smem ~17.9 KB; 5 blocks/SM at <=51 regs.
// ---------------------------------------------------------------------------
__global__ void __launch_bounds__(256, 5) main_kernel(const float* __restrict__ pc)
{
    extern __shared__ float sm[];
    __nv_bfloat16* bjl_h = (__nv_bfloat16*)sm;            // 64x64 bf16 = 8192 B
    __nv_bfloat16* alk_h = (__nv_bfloat16*)(sm + 2048);   // 64x68 bf16 = 8704 B (pitch 68)
    float* dispx = sm + 4224;              // 64 each, 16B aligned
    float* dispy = dispx + 64;
    float* dispz = dispy + 64;
    float* aqj_s = dispz + 64;             // 64
    float* red   = aqj_s + 64;             // 8 partials (one per warp)

    const int tid = threadIdx.x;
    const int b = blockIdx.x >> 6, i = blockIdx.x & 63;
    const float* pcb = pc + b * NN * 3;
    const float pix = pcb[i * 3], piy = pcb[i * 3 + 1], piz = pcb[i * 3 + 2];

    for (int n = tid; n < NN; n += blockDim.x) {
        dispx[n] = pcb[n * 3 + 0] - pix;
        dispy[n] = pcb[n * 3 + 1] - piy;
        dispz[n] = pcb[n * 3 + 2] - piz;
    }

    const float* g_ajk = g_att + (0 * BB + b) * 4096;
    const float* g_ajl = g_att + (1 * BB + b) * 4096;
    const float* g_akl = g_att + (2 * BB + b) * 4096;   // [k][l]
    const float* aqj   = g_att + (3 * BB + b) * 4096 + i * NN;
    const float* aqk   = g_att + (4 * BB + b) * 4096 + i * NN;
    const float* aql   = g_att + (5 * BB + b) * 4096 + i * NN;

    for (int idx = tid; idx < 4096; idx += blockDim.x) {
        int r = idx >> 6, c = idx & 63;
        bjl_h[idx] = __float2bfloat16(g_ajl[idx] + aql[c]);
        alk_h[r * 68 + c] = __float2bfloat16(g_akl[idx] + aqk[r]);  // aqk folded
    }
    for (int n = tid; n < NN; n += blockDim.x) aqj_s[n] = aqj[n];
    __syncthreads();

    const int k = tid & 63, jb = tid >> 6;
    const int j0base = jb * 16;
    const float dkx = dispx[k], dky = dispy[k], dkz = dispz[k];

    // ---- analytic det^2 half-sum for this thread's j subset ----
    float accD;
    {
        float qxx = 0, qxy = 0, qxz = 0, qyy = 0, qyz = 0, qzz = 0;
        #pragma unroll 4
        for (int jj = 0; jj < 16; ++jj) {
            float dx = dispx[j0base + jj], dy = dispy[j0base + jj], dz = dispz[j0base + jj];
            qxx = fmaf(dx, dx, qxx); qxy = fmaf(dx, dy, qxy); qxz = fmaf(dx, dz, qxz);
            qyy = fmaf(dy, dy, qyy); qyz = fmaf(dy, dz, qyz); qzz = fmaf(dz, dz, qzz);
        }
        const float* Mp = g_M + (b * NN + i) * 6;
        float Mxx = Mp[0], Mxy = Mp[1], Mxz = Mp[2], Myy = Mp[3], Myz = Mp[4], Mzz = Mp[5];
        // B = M * S, S = [dk]x (need all but B00)
        float B01 = fmaf(Mxz, dkx, -Mxx * dkz);
        float B02 = fmaf(Mxx, dky, -Mxy * dkx);
        float B10 = fmaf(Myy, dkz, -Myz * dky);
        float B11 = fmaf(Myz, dkx, -Mxy * dkz);
        float B12 = fmaf(Mxy, dky, -Myy * dkx);
        float B20 = fmaf(Myz, dkz, -Mzz * dky);
        float B21 = fmaf(Mzz, dkx, -Mxz * dkz);
        float B22 = fmaf(Mxz, dky, -Myz * dkx);
        // A = S^T * M * S (symmetric)
        float A00 = fmaf(dkz, B10, -dky * B20);
        float A01 = fmaf(dkz, B11, -dky * B21);
        float A02 = fmaf(dkz, B12, -dky * B22);
        float A11 = fmaf(dkx, B21, -dkz * B01);
        float A12 = fmaf(dkx, B22, -dkz * B02);
        float A22 = fmaf(dky, B02, -dkx * B12);
        accD = A00 * qxx + A11 * qyy + A22 * qzz
             + 2.f * (A01 * qxy + A02 * qxz + A12 * qyz);
    }

    U64 accT = 0;          // packed pair accumulator for sum tanh*det^2
    const __nv_bfloat16* alk_k = alk_h + k * 68;
    const float* gajk_k = g_ajk + k;

    // prefetch c0 (ajk) for first j-tile
    float pf0 = gajk_k[(j0base + 0) * NN];
    float pf1 = gajk_k[(j0base + 1) * NN];

    for (int jt = 0; jt < 16; jt += 2) {
        const float c00 = pf0 + aqj_s[j0base + jt];
        const float c01 = pf1 + aqj_s[j0base + jt + 1];
        if (jt + 2 < 16) {   // prefetch next tile's ajk under this tile's math
            pf0 = gajk_k[(j0base + jt + 2) * NN];
            pf1 = gajk_k[(j0base + jt + 3) * NN];
        }
        U32 c0b[2];
        c0b[0] = cvt2bf2(c00, c00);
        c0b[1] = cvt2bf2(c01, c01);
        U64 crx[2], cry[2], crz[2];
        #pragma unroll
        for (int u = 0; u < 2; ++u) {
            const int j = j0base + jt + u;
            const float djx = dispx[j], djy = dispy[j], djz = dispz[j];
            const float cx = fmaf(djy, dkz, -djz * dky);
            const float cy = fmaf(djz, dkx, -djx * dkz);
            const float cz = fmaf(djx, dky, -djy * dkx);
            crx[u] = pk2(cx, cx); cry[u] = pk2(cy, cy); crz[u] = pk2(cz, cz);
        }
        const __nv_bfloat16* bjlbase = bjl_h + (j0base + jt) * NN;

        #pragma unroll 1
        for (int l4 = 0; l4 < NN; l4 += 4) {
            // j-invariant loads, shared across the 2-j tile
            U64 ap = *(const U64*)(alk_k + l4);                  // 4 bf16, spread (2 wf)
            ulonglong2 xp = *(const ulonglong2*)(dispx + l4);    // broadcast f32x4
            ulonglong2 yp = *(const ulonglong2*)(dispy + l4);
            ulonglong2 zp = *(const ulonglong2*)(dispz + l4);
            const U32 ap0 = (U32)ap, ap1 = (U32)(ap >> 32);
            #pragma unroll
            for (int u = 0; u < 2; ++u) {
                U64 bp = *(const U64*)(bjlbase + u * NN + l4);   // 4 bf16, broadcast
                const U32 bp0 = (U32)bp, bp1 = (U32)(bp >> 32);
                U32 e0 = haddbf2(haddbf2(ap0, bp0), c0b[u]);    // = E/2 (bf16 pair)
                U32 e1 = haddbf2(haddbf2(ap1, bp1), c0b[u]);
                U32 t0 = tanhbf2(e0);
                U32 t1 = tanhbf2(e1);
                U64 d0 = fma2(crx[u], xp.x, fma2(cry[u], yp.x, mul2(crz[u], zp.x)));
                U64 d1 = fma2(crx[u], xp.y, fma2(cry[u], yp.y, mul2(crz[u], zp.y)));
                accT = fma2(bf2_to_f32x2(t0), mul2(d0, d0), accT);
                accT = fma2(bf2_to_f32x2(t1), mul2(d1, d1), accT);
            }
        }
    }

    float tlo, thi; upk2(accT, tlo, thi);
    float v = 0.5f * (tlo + thi) + 0.5f * accD;
    // warp reduce, then 8 partials through smem
    #pragma unroll
    for (int s = 16; s > 0; s >>= 1)
        v += __shfl_xor_sync(0xffffffffu, v, s);
    if ((tid & 31) == 0) red[tid >> 5] = v;
    __syncthreads();
    if (tid == 0) {
        float t = 0.f;
        #pragma unroll
        for (int w = 0; w < 8; ++w) t += red[w];
        g_agg[blockIdx.x] = t * (1.f / 262144.f);
    }
}

// ---------------------------------------------------------------------------
// Final: pool over anchors, 1->32->1 MLP with tanh-approx gelu.
// ---------------------------------------------------------------------------
__global__ void final_kernel(const float* __restrict__ W1, const float* __restrict__ b1,
                             const float* __restrict__ W2, const float* __restrict__ b2,
                             float* __restrict__ out)
{
    int b = threadIdx.x;
    if (b >= BB) return;
    float p = 0.f;
    for (int i = 0; i < NN; ++i) p += g_agg[b * NN + i];
    p *= (1.f / NN);
    float o = b2[0];
    for (int j = 0; j < 32; ++j) {
        float x = fmaf(p, W1[j], b1[j]);
        float inner = 0.7978845608028654f * (x + 0.044715f * x * x * x);
        float h = 0.5f * x * (1.f + tanhf(inner));
        o = fmaf(h, W2[j], o);
    }
    out[b] = o;
}

extern "C" void kernel_launch(void* const* d_in, const int* in_sizes, int n_in,
                              void* d_out, int out_size)
{
    const float* pc  = (const float*)d_in[0];
    const float* Wq  = (const float*)d_in[1];
    const float* bq  = (const float*)d_in[2];
    const float* Wk1 = (const float*)d_in[3];
    const float* bk1 = (const float*)d_in[4];
    const float* Wk2 = (const float*)d_in[5];
    const float* bk2 = (const float*)d_in[6];
    const float* Wk3 = (const float*)d_in[7];
    const float* bk3 = (const float*)d_in[8];
    const float* W1  = (const float*)d_in[9];
    const float* b1  = (const float*)d_in[10];
    const float* W2  = (const float*)d_in[11];
    const float* b2  = (const float*)d_in[12];
    float* out = (float*)d_out;

    // smem: 2048 (bjl bf16) + 2176 (alk bf16) + 3*64 + 64 + 8 floats = 17952 B
    const int MAIN_SMEM = (2048 + 2176 + 3 * 64 + 64 + 8) * (int)sizeof(float);
    cudaFuncSetAttribute(main_kernel, cudaFuncAttributeMaxDynamicSharedMemorySize, MAIN_SMEM);

    keys_kernel<<<dim3(4, 32), 256>>>(pc, Wq, bq, Wk1, bk1, Wk2, bk2, Wk3, bk3);
    att_kernel<<<dim3(6, 32), 256>>>();
    mmat_kernel<<<32, 64>>>(pc);
    main_kernel<<<BB * NN, 256, MAIN_SMEM>>>(pc);
    final_kernel<<<1, 32>>>(W1, b1, W2, b2, out);
}

// round 12
// speedup vs baseline: 1.0329x; 1.0329x over previous
#include <cuda_runtime.h>
#include <math.h>

#define BB 32
#define NN 64
#define DD 64
typedef unsigned long long U64;

// Scratch (no allocations allowed)
__device__ float g_keys[4 * BB * NN * DD];   // 4 key matrices per batch
__device__ float g_att[6 * BB * NN * NN];    // 6 att matrices (pre-scaled by scale/2)
__device__ float g_M[BB * NN * 6];           // per (b,i): sum_l dl dl^T (6 unique)
__device__ float g_agg[BB * NN];

// ---- packed f32x2 helpers (FFMA2 only reachable via PTX) ----
__device__ __forceinline__ U64 pk2(float a, float b) {
    U64 r; asm("mov.b64 %0,{%1,%2};" : "=l"(r) : "f"(a), "f"(b)); return r;
}
__device__ __forceinline__ void upk2(U64 v, float& a, float& b) {
    asm("mov.b64 {%0,%1},%2;" : "=f"(a), "=f"(b) : "l"(v));
}
__device__ __forceinline__ U64 add2(U64 a, U64 b) {
    U64 d; asm("add.rn.f32x2 %0,%1,%2;" : "=l"(d) : "l"(a), "l"(b)); return d;
}
__device__ __forceinline__ U64 mul2(U64 a, U64 b) {
    U64 d; asm("mul.rn.f32x2 %0,%1,%2;" : "=l"(d) : "l"(a), "l"(b)); return d;
}
__device__ __forceinline__ U64 fma2(U64 a, U64 b, U64 c) {
    U64 d; asm("fma.rn.f32x2 %0,%1,%2,%3;" : "=l"(d) : "l"(a), "l"(b), "l"(c)); return d;
}
__device__ __forceinline__ float tanh_ap(float x) {
    float y; asm("tanh.approx.f32 %0,%1;" : "=f"(y) : "f"(x)); return y;
}

// ---------------------------------------------------------------------------
// Keys: 3->64 dense for the 4 projections, to gmem. grid (4, 32), 256 thr.
// m==0 blocks additionally compute g_M (folds the old mmat_kernel launch).
// ---------------------------------------------------------------------------
__global__ void keys_kernel(const float* __restrict__ pc,
                            const float* __restrict__ Wq,  const float* __restrict__ bq,
                            const float* __restrict__ Wk1, const float* __restrict__ bk1,
                            const float* __restrict__ Wk2, const float* __restrict__ bk2,
                            const float* __restrict__ Wk3, const float* __restrict__ bk3)
{
    const int m = blockIdx.x, b = blockIdx.y, tid = threadIdx.x;
    const float* Ws[4] = {Wq, Wk1, Wk2, Wk3};
    const float* bs[4] = {bq, bk1, bk2, bk3};
    const float* W = Ws[m]; const float* bias = bs[m];
    const float* pcb = pc + b * NN * 3;
    float* out = g_keys + (m * BB + b) * NN * DD;
    for (int idx = tid; idx < NN * DD; idx += blockDim.x) {
        int n = idx >> 6, d = idx & 63;
        float p0 = pcb[n * 3], p1 = pcb[n * 3 + 1], p2 = pcb[n * 3 + 2];
        out[idx] = fmaf(p0, W[d], fmaf(p1, W[DD + d], fmaf(p2, W[2 * DD + d], bias[d])));
    }
    if (m == 0 && tid < NN) {
        float pix = pcb[tid * 3], piy = pcb[tid * 3 + 1], piz = pcb[tid * 3 + 2];
        float xx = 0, xy = 0, xz = 0, yy = 0, yz = 0, zz = 0;
        #pragma unroll 4
        for (int l = 0; l < NN; ++l) {
            float dx = pcb[l * 3] - pix, dy = pcb[l * 3 + 1] - piy, dz = pcb[l * 3 + 2] - piz;
            xx = fmaf(dx, dx, xx); xy = fmaf(dx, dy, xy); xz = fmaf(dx, dz, xz);
            yy = fmaf(dy, dy, yy); yz = fmaf(dy, dz, yz); zz = fmaf(dz, dz, zz);
        }
        float* o = g_M + (b * NN + tid) * 6;
        o[0] = xx; o[1] = xy; o[2] = xz; o[3] = yy; o[4] = yz; o[5] = zz;
    }
}

// ---------------------------------------------------------------------------
// Atts: 64x64 dot matrices, pre-scaled by scale/2 = 0.0625 (tanh half-arg).
// m: 0 ajk[j][k], 1 ajl[j][l], 2 akl[k][l] (k-major!), 3 aqj[i][j],
//    4 aqk[i][k], 5 aql[i][l].  grid (6, 32), 256 thr.
// Dot loop vectorized with LDS.128 on pitch-68 rows (16B aligned, CF).
// ---------------------------------------------------------------------------
__global__ void att_kernel()
{
    __shared__ float L[NN * 68];
    __shared__ float R[NN * 68];
    const int m = blockIdx.x, b = blockIdx.y, tid = threadIdx.x;
    const int lsel[6] = {1, 1, 2, 0, 0, 0};
    const int rsel[6] = {2, 3, 3, 1, 2, 3};
    const float* gl = g_keys + (lsel[m] * BB + b) * NN * DD;
    const float* gr = g_keys + (rsel[m] * BB + b) * NN * DD;
    for (int idx = tid; idx < NN * DD; idx += blockDim.x) {
        int n = idx >> 6, d = idx & 63;
        L[n * 68 + d] = gl[idx];
        R[n * 68 + d] = gr[idx];
    }
    __syncthreads();
    const float SC = 0.0625f;  // (1/sqrt(64)) / 2
    float* outm = g_att + (m * BB + b) * NN * NN;
    for (int idx = tid; idx < NN * NN; idx += blockDim.x) {
        int r = idx >> 6, c = idx & 63;          // r warp-uniform, c lane-spread
        const float4* L4 = (const float4*)(L + r * 68);
        const float4* R4 = (const float4*)(R + c * 68);
        float s = 0.f;
        #pragma unroll
        for (int d4 = 0; d4 < DD / 4; ++d4) {
            float4 lv = L4[d4], rv = R4[d4];
            s = fmaf(lv.x, rv.x, s); s = fmaf(lv.y, rv.y, s);
            s = fmaf(lv.z, rv.z, s); s = fmaf(lv.w, rv.w, s);
        }
        outm[idx] = SC * s;
    }
}

// ---------------------------------------------------------------------------
// Main: one block per (b,i). 256 thr: k = tid&63, jb = tid>>6 (16 j each).
// f32x2 mainloop (proven R10 structure): j-tile 2 shares the spread alk load
// and disp broadcasts; one tanh.approx.f32 per element; det^2 half-sum folded
// analytically (A:Q contraction). Two packed accumulators (one per tile-j)
// halve the serial FFMA2 chain. 6 blocks/SM via reg cap 42.
// ---------------------------------------------------------------------------
__global__ void __launch_bounds__(256, 6) main_kernel(const float* __restrict__ pc)
{
    extern __shared__ float sm[];
    float* bjl_s = sm;                     // 4096: ajl + aql[l]
    float* alkT  = sm + 4096;              // 64*68: akl[k][l] + aqk[k], pitch 68
    float* dispx = sm + 4096 + 4352;       // 64 each, 16B aligned
    float* dispy = dispx + 64;
    float* dispz = dispy + 64;
    float* aqj_s = dispz + 64;             // 64
    float* red   = aqj_s + 64;             // 8 partials (one per warp)

    const int tid = threadIdx.x;
    const int b = blockIdx.x >> 6, i = blockIdx.x & 63;
    const float* pcb = pc + b * NN * 3;
    const float pix = pcb[i * 3], piy = pcb[i * 3 + 1], piz = pcb[i * 3 + 2];

    for (int n = tid; n < NN; n += blockDim.x) {
        dispx[n] = pcb[n * 3 + 0] - pix;
        dispy[n] = pcb[n * 3 + 1] - piy;
        dispz[n] = pcb[n * 3 + 2] - piz;
    }

    const float* g_ajk = g_att + (0 * BB + b) * 4096;
    const float* g_ajl = g_att + (1 * BB + b) * 4096;
    const float* g_akl = g_att + (2 * BB + b) * 4096;   // [k][l]
    const float* aqj   = g_att + (3 * BB + b) * 4096 + i * NN;
    const float* aqk   = g_att + (4 * BB + b) * 4096 + i * NN;
    const float* aql   = g_att + (5 * BB + b) * 4096 + i * NN;

    for (int idx = tid; idx < 4096; idx += blockDim.x) {
        int r = idx >> 6, c = idx & 63;
        bjl_s[idx] = g_ajl[idx] + aql[c];
        alkT[r * 68 + c] = g_akl[idx] + aqk[r];   // fold aqk(k) in here
    }
    for (int n = tid; n < NN; n += blockDim.x) aqj_s[n] = aqj[n];
    __syncthreads();

    const int k = tid & 63, jb = tid >> 6;
    const int j0base = jb * 16;
    const float dkx = dispx[k], dky = dispy[k], dkz = dispz[k];

    // ---- analytic det^2 half-sum for this thread's j subset ----
    float accD;
    {
        float qxx = 0, qxy = 0, qxz = 0, qyy = 0, qyz = 0, qzz = 0;
        #pragma unroll 4
        for (int jj = 0; jj < 16; ++jj) {
            float dx = dispx[j0base + jj], dy = dispy[j0base + jj], dz = dispz[j0base + jj];
            qxx = fmaf(dx, dx, qxx); qxy = fmaf(dx, dy, qxy); qxz = fmaf(dx, dz, qxz);
            qyy = fmaf(dy, dy, qyy); qyz = fmaf(dy, dz, qyz); qzz = fmaf(dz, dz, qzz);
        }
        const float* Mp = g_M + (b * NN + i) * 6;
        float Mxx = Mp[0], Mxy = Mp[1], Mxz = Mp[2], Myy = Mp[3], Myz = Mp[4], Mzz = Mp[5];
        // B = M * S, S = [dk]x (need all but B00)
        float B01 = fmaf(Mxz, dkx, -Mxx * dkz);
        float B02 = fmaf(Mxx, dky, -Mxy * dkx);
        float B10 = fmaf(Myy, dkz, -Myz * dky);
        float B11 = fmaf(Myz, dkx, -Mxy * dkz);
        float B12 = fmaf(Mxy, dky, -Myy * dkx);
        float B20 = fmaf(Myz, dkz, -Mzz * dky);
        float B21 = fmaf(Mzz, dkx, -Mxz * dkz);
        float B22 = fmaf(Mxz, dky, -Myz * dkx);
        // A = S^T * M * S (symmetric)
        float A00 = fmaf(dkz, B10, -dky * B20);
        float A01 = fmaf(dkz, B11, -dky * B21);
        float A02 = fmaf(dkz, B12, -dky * B22);
        float A11 = fmaf(dkx, B21, -dkz * B01);
        float A12 = fmaf(dkx, B22, -dkz * B02);
        float A22 = fmaf(dky, B02, -dkx * B12);
        accD = A00 * qxx + A11 * qyy + A22 * qzz
             + 2.f * (A01 * qxy + A02 * qxz + A12 * qyz);
    }

    U64 accT0 = 0, accT1 = 0;   // one packed accumulator per tile-j (shorter chains)
    const float* alkrow = alkT + k * 68;
    const float* gajk_k = g_ajk + k;

    // prefetch c0 (ajk) for first j-tile
    float pf0 = gajk_k[(j0base + 0) * NN];
    float pf1 = gajk_k[(j0base + 1) * NN];

    for (int jt = 0; jt < 16; jt += 2) {
        const float c00 = pf0 + aqj_s[j0base + jt];
        const float c01 = pf1 + aqj_s[j0base + jt + 1];
        if (jt + 2 < 16) {   // prefetch next tile's ajk under this tile's math
            pf0 = gajk_k[(j0base + jt + 2) * NN];
            pf1 = gajk_k[(j0base + jt + 3) * NN];
        }
        U64 crx[2], cry[2], crz[2], c0p[2];
        c0p[0] = pk2(c00, c00); c0p[1] = pk2(c01, c01);
        #pragma unroll
        for (int u = 0; u < 2; ++u) {
            const int j = j0base + jt + u;
            const float djx = dispx[j], djy = dispy[j], djz = dispz[j];
            const float cx = fmaf(djy, dkz, -djz * dky);
            const float cy = fmaf(djz, dkx, -djx * dkz);
            const float cz = fmaf(djx, dky, -djy * dkx);
            crx[u] = pk2(cx, cx); cry[u] = pk2(cy, cy); crz[u] = pk2(cz, cz);
        }
        const float* bjlbase = bjl_s + (j0base + jt) * NN;

        #pragma unroll 1
        for (int l4 = 0; l4 < NN; l4 += 4) {
            // j-invariant loads, shared across the 2-j tile
            ulonglong2 ap = *(const ulonglong2*)(alkrow + l4);   // spread, 4 wf
            ulonglong2 xp = *(const ulonglong2*)(dispx + l4);    // broadcast
            ulonglong2 yp = *(const ulonglong2*)(dispy + l4);
            ulonglong2 zp = *(const ulonglong2*)(dispz + l4);
            {   // u = 0
                ulonglong2 bp = *(const ulonglong2*)(bjlbase + l4);
                U64 e0 = add2(add2(c0p[0], bp.x), ap.x);
                U64 e1 = add2(add2(c0p[0], bp.y), ap.y);
                U64 d0 = fma2(crx[0], xp.x, fma2(cry[0], yp.x, mul2(crz[0], zp.x)));
                U64 d1 = fma2(crx[0], xp.y, fma2(cry[0], yp.y, mul2(crz[0], zp.y)));
                float ea, eb, ec, ed;
                upk2(e0, ea, eb); upk2(e1, ec, ed);
                U64 t0 = pk2(tanh_ap(ea), tanh_ap(eb));
                U64 t1 = pk2(tanh_ap(ec), tanh_ap(ed));
                accT0 = fma2(t0, mul2(d0, d0), accT0);
                accT0 = fma2(t1, mul2(d1, d1), accT0);
            }
            {   // u = 1
                ulonglong2 bp = *(const ulonglong2*)(bjlbase + NN + l4);
                U64 e0 = add2(add2(c0p[1], bp.x), ap.x);
                U64 e1 = add2(add2(c0p[1], bp.y), ap.y);
                U64 d0 = fma2(crx[1], xp.x, fma2(cry[1], yp.x, mul2(crz[1], zp.x)));
                U64 d1 = fma2(crx[1], xp.y, fma2(cry[1], yp.y, mul2(crz[1], zp.y)));
                float ea, eb, ec, ed;
                upk2(e0, ea, eb); upk2(e1, ec, ed);
                U64 t0 = pk2(tanh_ap(ea), tanh_ap(eb));
                U64 t1 = pk2(tanh_ap(ec), tanh_ap(ed));
                accT1 = fma2(t0, mul2(d0, d0), accT1);
                accT1 = fma2(t1, mul2(d1, d1), accT1);
            }
        }
    }

    U64 accT = add2(accT0, accT1);
    float tlo, thi; upk2(accT, tlo, thi);
    float v = 0.5f * (tlo + thi) + 0.5f * accD;
    // warp reduce, then 8 partials through smem
    #pragma unroll
    for (int s = 16; s > 0; s >>= 1)
        v += __shfl_xor_sync(0xffffffffu, v, s);
    if ((tid & 31) == 0) red[tid >> 5] = v;
    __syncthreads();
    if (tid == 0) {
        float t = 0.f;
        #pragma unroll
        for (int w = 0; w < 8; ++w) t += red[w];
        g_agg[blockIdx.x] = t * (1.f / 262144.f);
    }
}

// ---------------------------------------------------------------------------
// Final: pool over anchors, 1->32->1 MLP with tanh-approx gelu.
// ---------------------------------------------------------------------------
__global__ void final_kernel(const float* __restrict__ W1, const float* __restrict__ b1,
                             const float* __restrict__ W2, const float* __restrict__ b2,
                             float* __restrict__ out)
{
    int b = threadIdx.x;
    if (b >= BB) return;
    float p = 0.f;
    for (int i = 0; i < NN; ++i) p += g_agg[b * NN + i];
    p *= (1.f / NN);
    float o = b2[0];
    for (int j = 0; j < 32; ++j) {
        float x = fmaf(p, W1[j], b1[j]);
        float inner = 0.7978845608028654f * (x + 0.044715f * x * x * x);
        float h = 0.5f * x * (1.f + tanhf(inner));
        o = fmaf(h, W2[j], o);
    }
    out[b] = o;
}

extern "C" void kernel_launch(void* const* d_in, const int* in_sizes, int n_in,
                              void* d_out, int out_size)
{
    const float* pc  = (const float*)d_in[0];
    const float* Wq  = (const float*)d_in[1];
    const float* bq  = (const float*)d_in[2];
    const float* Wk1 = (const float*)d_in[3];
    const float* bk1 = (const float*)d_in[4];
    const float* Wk2 = (const float*)d_in[5];
    const float* bk2 = (const float*)d_in[6];
    const float* Wk3 = (const float*)d_in[7];
    const float* bk3 = (const float*)d_in[8];
    const float* W1  = (const float*)d_in[9];
    const float* b1  = (const float*)d_in[10];
    const float* W2  = (const float*)d_in[11];
    const float* b2  = (const float*)d_in[12];
    float* out = (float*)d_out;

    // smem: 4096 + 4352 + 3*64 + 64 + 8 floats = 8712 floats = 34848 B
    const int MAIN_SMEM = (4096 + 4352 + 3 * 64 + 64 + 8) * (int)sizeof(float);
    cudaFuncSetAttribute(main_kernel, cudaFuncAttributeMaxDynamicSharedMemorySize, MAIN_SMEM);

    keys_kernel<<<dim3(4, 32), 256>>>(pc, Wq, bq, Wk1, bk1, Wk2, bk2, Wk3, bk3);
    att_kernel<<<dim3(6, 32), 256>>>();
    main_kernel<<<BB * NN, 256, MAIN_SMEM>>>(pc);
    final_kernel<<<1, 32>>>(W1, b1, W2, b2, out);
}

// round 13
// speedup vs baseline: 1.2220x; 1.1831x over previous
#include <cuda_runtime.h>
#include <math.h>

#define BB 32
#define NN 64
#define DD 64
typedef unsigned long long U64;

// Scratch (no allocations allowed)
__device__ float g_keys[4 * BB * NN * DD];   // 4 key matrices per batch
__device__ float g_att[6 * BB * NN * NN];    // 6 att matrices (pre-scaled by scale/2)
__device__ float g_M[BB * NN * 6];           // per (b,i): sum_l dl dl^T (6 unique)
__device__ float g_agg[BB * NN];

// ---- packed f32x2 helpers (FFMA2 only reachable via PTX) ----
__device__ __forceinline__ U64 pk2(float a, float b) {
    U64 r; asm("mov.b64 %0,{%1,%2};" : "=l"(r) : "f"(a), "f"(b)); return r;
}
__device__ __forceinline__ void upk2(U64 v, float& a, float& b) {
    asm("mov.b64 {%0,%1},%2;" : "=f"(a), "=f"(b) : "l"(v));
}
__device__ __forceinline__ U64 add2(U64 a, U64 b) {
    U64 d; asm("add.rn.f32x2 %0,%1,%2;" : "=l"(d) : "l"(a), "l"(b)); return d;
}
__device__ __forceinline__ U64 mul2(U64 a, U64 b) {
    U64 d; asm("mul.rn.f32x2 %0,%1,%2;" : "=l"(d) : "l"(a), "l"(b)); return d;
}
__device__ __forceinline__ U64 fma2(U64 a, U64 b, U64 c) {
    U64 d; asm("fma.rn.f32x2 %0,%1,%2,%3;" : "=l"(d) : "l"(a), "l"(b), "l"(c)); return d;
}
__device__ __forceinline__ float tanh_ap(float x) {
    float y; asm("tanh.approx.f32 %0,%1;" : "=f"(y) : "f"(x)); return y;
}

// ---------------------------------------------------------------------------
// Keys: 3->64 dense for the 4 projections, to gmem. grid (4, 32), 256 thr.
// m==0 blocks additionally compute g_M (folds the old mmat_kernel launch).
// ---------------------------------------------------------------------------
__global__ void keys_kernel(const float* __restrict__ pc,
                            const float* __restrict__ Wq,  const float* __restrict__ bq,
                            const float* __restrict__ Wk1, const float* __restrict__ bk1,
                            const float* __restrict__ Wk2, const float* __restrict__ bk2,
                            const float* __restrict__ Wk3, const float* __restrict__ bk3)
{
    const int m = blockIdx.x, b = blockIdx.y, tid = threadIdx.x;
    const float* Ws[4] = {Wq, Wk1, Wk2, Wk3};
    const float* bs[4] = {bq, bk1, bk2, bk3};
    const float* W = Ws[m]; const float* bias = bs[m];
    const float* pcb = pc + b * NN * 3;
    float* out = g_keys + (m * BB + b) * NN * DD;
    for (int idx = tid; idx < NN * DD; idx += blockDim.x) {
        int n = idx >> 6, d = idx & 63;
        float p0 = pcb[n * 3], p1 = pcb[n * 3 + 1], p2 = pcb[n * 3 + 2];
        out[idx] = fmaf(p0, W[d], fmaf(p1, W[DD + d], fmaf(p2, W[2 * DD + d], bias[d])));
    }
    if (m == 0 && tid < NN) {
        float pix = pcb[tid * 3], piy = pcb[tid * 3 + 1], piz = pcb[tid * 3 + 2];
        float xx = 0, xy = 0, xz = 0, yy = 0, yz = 0, zz = 0;
        #pragma unroll 4
        for (int l = 0; l < NN; ++l) {
            float dx = pcb[l * 3] - pix, dy = pcb[l * 3 + 1] - piy, dz = pcb[l * 3 + 2] - piz;
            xx = fmaf(dx, dx, xx); xy = fmaf(dx, dy, xy); xz = fmaf(dx, dz, xz);
            yy = fmaf(dy, dy, yy); yz = fmaf(dy, dz, yz); zz = fmaf(dz, dz, zz);
        }
        float* o = g_M + (b * NN + tid) * 6;
        o[0] = xx; o[1] = xy; o[2] = xz; o[3] = yy; o[4] = yz; o[5] = zz;
    }
}

// ---------------------------------------------------------------------------
// Atts: 64x64 dot matrices, pre-scaled by scale/2 = 0.0625 (tanh half-arg).
// m: 0 ajk[j][k], 1 ajl[j][l], 2 akl[k][l] (k-major!), 3 aqj[i][j],
//    4 aqk[i][k], 5 aql[i][l].  grid (6, 32), 256 thr.
// Dot loop vectorized with LDS.128 on pitch-68 rows (16B aligned, CF).
// ---------------------------------------------------------------------------
__global__ void att_kernel()
{
    __shared__ float L[NN * 68];
    __shared__ float R[NN * 68];
    const int m = blockIdx.x, b = blockIdx.y, tid = threadIdx.x;
    const int lsel[6] = {1, 1, 2, 0, 0, 0};
    const int rsel[6] = {2, 3, 3, 1, 2, 3};
    const float* gl = g_keys + (lsel[m] * BB + b) * NN * DD;
    const float* gr = g_keys + (rsel[m] * BB + b) * NN * DD;
    for (int idx = tid; idx < NN * DD; idx += blockDim.x) {
        int n = idx >> 6, d = idx & 63;
        L[n * 68 + d] = gl[idx];
        R[n * 68 + d] = gr[idx];
    }
    __syncthreads();
    const float SC = 0.0625f;  // (1/sqrt(64)) / 2
    float* outm = g_att + (m * BB + b) * NN * NN;
    for (int idx = tid; idx < NN * NN; idx += blockDim.x) {
        int r = idx >> 6, c = idx & 63;          // r warp-uniform, c lane-spread
        const float4* L4 = (const float4*)(L + r * 68);
        const float4* R4 = (const float4*)(R + c * 68);
        float s = 0.f;
        #pragma unroll
        for (int d4 = 0; d4 < DD / 4; ++d4) {
            float4 lv = L4[d4], rv = R4[d4];
            s = fmaf(lv.x, rv.x, s); s = fmaf(lv.y, rv.y, s);
            s = fmaf(lv.z, rv.z, s); s = fmaf(lv.w, rv.w, s);
        }
        outm[idx] = SC * s;
    }
}

// ---------------------------------------------------------------------------
// Main: one block per (b,i). 256 thr: k = tid&63, jb = tid>>6 (16 j each).
// Exact R10 structure (launch_bounds(256,5), proven 157us / 48 regs):
// j-tile 2 shares the spread alk load and disp broadcasts; one
// tanh.approx.f32 per element; det^2 half-sum folded analytically
// (A:Q contraction). Only change vs R10: two packed accumulators
// (+2 regs, halves the serial accumulate chain).
// ---------------------------------------------------------------------------
__global__ void __launch_bounds__(256, 5) main_kernel(const float* __restrict__ pc)
{
    extern __shared__ float sm[];
    float* bjl_s = sm;                     // 4096: ajl + aql[l]
    float* alkT  = sm + 4096;              // 64*68: akl[k][l] + aqk[k], pitch 68
    float* dispx = sm + 4096 + 4352;       // 64 each, 16B aligned
    float* dispy = dispx + 64;
    float* dispz = dispy + 64;
    float* aqj_s = dispz + 64;             // 64
    float* red   = aqj_s + 64;             // 8 partials (one per warp)

    const int tid = threadIdx.x;
    const int b = blockIdx.x >> 6, i = blockIdx.x & 63;
    const float* pcb = pc + b * NN * 3;
    const float pix = pcb[i * 3], piy = pcb[i * 3 + 1], piz = pcb[i * 3 + 2];

    for (int n = tid; n < NN; n += blockDim.x) {
        dispx[n] = pcb[n * 3 + 0] - pix;
        dispy[n] = pcb[n * 3 + 1] - piy;
        dispz[n] = pcb[n * 3 + 2] - piz;
    }

    const float* g_ajk = g_att + (0 * BB + b) * 4096;
    const float* g_ajl = g_att + (1 * BB + b) * 4096;
    const float* g_akl = g_att + (2 * BB + b) * 4096;   // [k][l]
    const float* aqj   = g_att + (3 * BB + b) * 4096 + i * NN;
    const float* aqk   = g_att + (4 * BB + b) * 4096 + i * NN;
    const float* aql   = g_att + (5 * BB + b) * 4096 + i * NN;

    for (int idx = tid; idx < 4096; idx += blockDim.x) {
        int r = idx >> 6, c = idx & 63;
        bjl_s[idx] = g_ajl[idx] + aql[c];
        alkT[r * 68 + c] = g_akl[idx] + aqk[r];   // fold aqk(k) in here
    }
    for (int n = tid; n < NN; n += blockDim.x) aqj_s[n] = aqj[n];
    __syncthreads();

    const int k = tid & 63, jb = tid >> 6;
    const int j0base = jb * 16;
    const float dkx = dispx[k], dky = dispy[k], dkz = dispz[k];

    // ---- analytic det^2 half-sum for this thread's j subset ----
    float accD;
    {
        float qxx = 0, qxy = 0, qxz = 0, qyy = 0, qyz = 0, qzz = 0;
        #pragma unroll 4
        for (int jj = 0; jj < 16; ++jj) {
            float dx = dispx[j0base + jj], dy = dispy[j0base + jj], dz = dispz[j0base + jj];
            qxx = fmaf(dx, dx, qxx); qxy = fmaf(dx, dy, qxy); qxz = fmaf(dx, dz, qxz);
            qyy = fmaf(dy, dy, qyy); qyz = fmaf(dy, dz, qyz); qzz = fmaf(dz, dz, qzz);
        }
        const float* Mp = g_M + (b * NN + i) * 6;
        float Mxx = Mp[0], Mxy = Mp[1], Mxz = Mp[2], Myy = Mp[3], Myz = Mp[4], Mzz = Mp[5];
        // B = M * S, S = [dk]x (need all but B00)
        float B01 = fmaf(Mxz, dkx, -Mxx * dkz);
        float B02 = fmaf(Mxx, dky, -Mxy * dkx);
        float B10 = fmaf(Myy, dkz, -Myz * dky);
        float B11 = fmaf(Myz, dkx, -Mxy * dkz);
        float B12 = fmaf(Mxy, dky, -Myy * dkx);
        float B20 = fmaf(Myz, dkz, -Mzz * dky);
        float B21 = fmaf(Mzz, dkx, -Mxz * dkz);
        float B22 = fmaf(Mxz, dky, -Myz * dkx);
        // A = S^T * M * S (symmetric)
        float A00 = fmaf(dkz, B10, -dky * B20);
        float A01 = fmaf(dkz, B11, -dky * B21);
        float A02 = fmaf(dkz, B12, -dky * B22);
        float A11 = fmaf(dkx, B21, -dkz * B01);
        float A12 = fmaf(dkx, B22, -dkz * B02);
        float A22 = fmaf(dky, B02, -dkx * B12);
        accD = A00 * qxx + A11 * qyy + A22 * qzz
             + 2.f * (A01 * qxy + A02 * qxz + A12 * qyz);
    }

    U64 accT0 = 0, accT1 = 0;   // split accumulators: half the serial chain
    const float* alkrow = alkT + k * 68;
    const float* gajk_k = g_ajk + k;

    // prefetch c0 (ajk) for first j-tile
    float pf0 = gajk_k[(j0base + 0) * NN];
    float pf1 = gajk_k[(j0base + 1) * NN];

    for (int jt = 0; jt < 16; jt += 2) {
        const float c00 = pf0 + aqj_s[j0base + jt];
        const float c01 = pf1 + aqj_s[j0base + jt + 1];
        if (jt + 2 < 16) {   // prefetch next tile's ajk under this tile's math
            pf0 = gajk_k[(j0base + jt + 2) * NN];
            pf1 = gajk_k[(j0base + jt + 3) * NN];
        }
        U64 crx[2], cry[2], crz[2], c0p[2];
        c0p[0] = pk2(c00, c00); c0p[1] = pk2(c01, c01);
        #pragma unroll
        for (int u = 0; u < 2; ++u) {
            const int j = j0base + jt + u;
            const float djx = dispx[j], djy = dispy[j], djz = dispz[j];
            const float cx = fmaf(djy, dkz, -djz * dky);
            const float cy = fmaf(djz, dkx, -djx * dkz);
            const float cz = fmaf(djx, dky, -djy * dkx);
            crx[u] = pk2(cx, cx); cry[u] = pk2(cy, cy); crz[u] = pk2(cz, cz);
        }
        const float* bjlbase = bjl_s + (j0base + jt) * NN;

        #pragma unroll 1
        for (int l4 = 0; l4 < NN; l4 += 4) {
            // j-invariant loads, shared across the 2-j tile
            ulonglong2 ap = *(const ulonglong2*)(alkrow + l4);   // spread, 4 wf
            ulonglong2 xp = *(const ulonglong2*)(dispx + l4);    // broadcast
            ulonglong2 yp = *(const ulonglong2*)(dispy + l4);
            ulonglong2 zp = *(const ulonglong2*)(dispz + l4);
            #pragma unroll
            for (int u = 0; u < 2; ++u) {
                ulonglong2 bp = *(const ulonglong2*)(bjlbase + u * NN + l4); // broadcast
                U64 e0 = add2(add2(c0p[u], bp.x), ap.x);   // = E/2 for (l4, l4+1)
                U64 e1 = add2(add2(c0p[u], bp.y), ap.y);
                U64 d0 = fma2(crx[u], xp.x, fma2(cry[u], yp.x, mul2(crz[u], zp.x)));
                U64 d1 = fma2(crx[u], xp.y, fma2(cry[u], yp.y, mul2(crz[u], zp.y)));
                float ea, eb, ec, ed;
                upk2(e0, ea, eb); upk2(e1, ec, ed);
                U64 t0 = pk2(tanh_ap(ea), tanh_ap(eb));
                U64 t1 = pk2(tanh_ap(ec), tanh_ap(ed));
                if (u == 0) {
                    accT0 = fma2(t0, mul2(d0, d0), accT0);
                    accT0 = fma2(t1, mul2(d1, d1), accT0);
                } else {
                    accT1 = fma2(t0, mul2(d0, d0), accT1);
                    accT1 = fma2(t1, mul2(d1, d1), accT1);
                }
            }
        }
    }

    U64 accT = add2(accT0, accT1);
    float tlo, thi; upk2(accT, tlo, thi);
    float v = 0.5f * (tlo + thi) + 0.5f * accD;
    // warp reduce, then 8 partials through smem
    #pragma unroll
    for (int s = 16; s > 0; s >>= 1)
        v += __shfl_xor_sync(0xffffffffu, v, s);
    if ((tid & 31) == 0) red[tid >> 5] = v;
    __syncthreads();
    if (tid == 0) {
        float t = 0.f;
        #pragma unroll
        for (int w = 0; w < 8; ++w) t += red[w];
        g_agg[blockIdx.x] = t * (1.f / 262144.f);
    }
}

// ---------------------------------------------------------------------------
// Final: pool over anchors, 1->32->1 MLP with tanh-approx gelu.
// ---------------------------------------------------------------------------
__global__ void final_kernel(const float* __restrict__ W1, const float* __restrict__ b1,
                             const float* __restrict__ W2, const float* __restrict__ b2,
                             float* __restrict__ out)
{
    int b = threadIdx.x;
    if (b >= BB) return;
    float p = 0.f;
    for (int i = 0; i < NN; ++i) p += g_agg[b * NN + i];
    p *= (1.f / NN);
    float o = b2[0];
    for (int j = 0; j < 32; ++j) {
        float x = fmaf(p, W1[j], b1[j]);
        float inner = 0.7978845608028654f * (x + 0.044715f * x * x * x);
        float h = 0.5f * x * (1.f + tanhf(inner));
        o = fmaf(h, W2[j], o);
    }
    out[b] = o;
}

extern "C" void kernel_launch(void* const* d_in, const int* in_sizes, int n_in,
                              void* d_out, int out_size)
{
    const float* pc  = (const float*)d_in[0];
    const float* Wq  = (const float*)d_in[1];
    const float* bq  = (const float*)d_in[2];
    const float* Wk1 = (const float*)d_in[3];
    const float* bk1 = (const float*)d_in[4];
    const float* Wk2 = (const float*)d_in[5];
    const float* bk2 = (const float*)d_in[6];
    const float* Wk3 = (const float*)d_in[7];
    const float* bk3 = (const float*)d_in[8];
    const float* W1  = (const float*)d_in[9];
    const float* b1  = (const float*)d_in[10];
    const float* W2  = (const float*)d_in[11];
    const float* b2  = (const float*)d_in[12];
    float* out = (float*)d_out;

    // smem: 4096 + 4352 + 3*64 + 64 + 8 floats = 8712 floats = 34848 B
    const int MAIN_SMEM = (4096 + 4352 + 3 * 64 + 64 + 8) * (int)sizeof(float);
    cudaFuncSetAttribute(main_kernel, cudaFuncAttributeMaxDynamicSharedMemorySize, MAIN_SMEM);

    keys_kernel<<<dim3(4, 32), 256>>>(pc, Wq, bq, Wk1, bk1, Wk2, bk2, Wk3, bk3);
    att_kernel<<<dim3(6, 32), 256>>>();
    main_kernel<<<BB * NN, 256, MAIN_SMEM>>>(pc);
    final_kernel<<<1, 32>>>(W1, b1, W2, b2, out);
}

// round 14
// speedup vs baseline: 1.2959x; 1.0605x over previous
#include <cuda_runtime.h>
#include <math.h>

#define BB 32
#define NN 64
#define DD 64
typedef unsigned long long U64;

// Scratch (no allocations allowed)
__device__ float g_keys[4 * BB * NN * DD];   // 4 key matrices per batch
__device__ float g_att[6 * BB * NN * NN];    // 6 att matrices (pre-scaled by scale/2)
__device__ float g_M[BB * NN * 6];           // per (b,i): sum_l dl dl^T (6 unique)
__device__ float g_agg[BB * NN];

// ---- packed f32x2 helpers (FFMA2 only reachable via PTX) ----
__device__ __forceinline__ U64 pk2(float a, float b) {
    U64 r; asm("mov.b64 %0,{%1,%2};" : "=l"(r) : "f"(a), "f"(b)); return r;
}
__device__ __forceinline__ void upk2(U64 v, float& a, float& b) {
    asm("mov.b64 {%0,%1},%2;" : "=f"(a), "=f"(b) : "l"(v));
}
__device__ __forceinline__ U64 add2(U64 a, U64 b) {
    U64 d; asm("add.rn.f32x2 %0,%1,%2;" : "=l"(d) : "l"(a), "l"(b)); return d;
}
__device__ __forceinline__ U64 mul2(U64 a, U64 b) {
    U64 d; asm("mul.rn.f32x2 %0,%1,%2;" : "=l"(d) : "l"(a), "l"(b)); return d;
}
__device__ __forceinline__ U64 fma2(U64 a, U64 b, U64 c) {
    U64 d; asm("fma.rn.f32x2 %0,%1,%2,%3;" : "=l"(d) : "l"(a), "l"(b), "l"(c)); return d;
}
__device__ __forceinline__ float tanh_ap(float x) {
    float y; asm("tanh.approx.f32 %0,%1;" : "=f"(y) : "f"(x)); return y;
}

// ---------------------------------------------------------------------------
// Keys: 3->64 dense for the 4 projections, to gmem. grid (4, 32), 256 thr.
// m==0 blocks additionally compute g_M (folds the old mmat_kernel launch).
// ---------------------------------------------------------------------------
__global__ void keys_kernel(const float* __restrict__ pc,
                            const float* __restrict__ Wq,  const float* __restrict__ bq,
                            const float* __restrict__ Wk1, const float* __restrict__ bk1,
                            const float* __restrict__ Wk2, const float* __restrict__ bk2,
                            const float* __restrict__ Wk3, const float* __restrict__ bk3)
{
    const int m = blockIdx.x, b = blockIdx.y, tid = threadIdx.x;
    const float* Ws[4] = {Wq, Wk1, Wk2, Wk3};
    const float* bs[4] = {bq, bk1, bk2, bk3};
    const float* W = Ws[m]; const float* bias = bs[m];
    const float* pcb = pc + b * NN * 3;
    float* out = g_keys + (m * BB + b) * NN * DD;
    for (int idx = tid; idx < NN * DD; idx += blockDim.x) {
        int n = idx >> 6, d = idx & 63;
        float p0 = pcb[n * 3], p1 = pcb[n * 3 + 1], p2 = pcb[n * 3 + 2];
        out[idx] = fmaf(p0, W[d], fmaf(p1, W[DD + d], fmaf(p2, W[2 * DD + d], bias[d])));
    }
    if (m == 0 && tid < NN) {
        float pix = pcb[tid * 3], piy = pcb[tid * 3 + 1], piz = pcb[tid * 3 + 2];
        float xx = 0, xy = 0, xz = 0, yy = 0, yz = 0, zz = 0;
        #pragma unroll 4
        for (int l = 0; l < NN; ++l) {
            float dx = pcb[l * 3] - pix, dy = pcb[l * 3 + 1] - piy, dz = pcb[l * 3 + 2] - piz;
            xx = fmaf(dx, dx, xx); xy = fmaf(dx, dy, xy); xz = fmaf(dx, dz, xz);
            yy = fmaf(dy, dy, yy); yz = fmaf(dy, dz, yz); zz = fmaf(dz, dz, zz);
        }
        float* o = g_M + (b * NN + tid) * 6;
        o[0] = xx; o[1] = xy; o[2] = xz; o[3] = yy; o[4] = yz; o[5] = zz;
    }
}

// ---------------------------------------------------------------------------
// Atts: 64x64 dot matrices, pre-scaled by scale/2 = 0.0625 (tanh half-arg).
// m: 0 ajk[j][k], 1 ajl[j][l], 2 akl[k][l] (k-major!), 3 aqj[i][j],
//    4 aqk[i][k], 5 aql[i][l].  grid (6, 32, 2) — z splits output rows so
//    384 blocks cover the chip (was 192, 1.3/SM latency-bound).
// ---------------------------------------------------------------------------
__global__ void att_kernel()
{
    __shared__ float L[32 * 68];
    __shared__ float R[NN * 68];
    const int m = blockIdx.x, b = blockIdx.y, z = blockIdx.z, tid = threadIdx.x;
    const int lsel[6] = {1, 1, 2, 0, 0, 0};
    const int rsel[6] = {2, 3, 3, 1, 2, 3};
    const float* gl = g_keys + (lsel[m] * BB + b) * NN * DD;
    const float* gr = g_keys + (rsel[m] * BB + b) * NN * DD;
    for (int idx = tid; idx < 32 * DD; idx += blockDim.x) {
        int n = idx >> 6, d = idx & 63;
        L[n * 68 + d] = gl[(z * 32 + n) * DD + d];
    }
    for (int idx = tid; idx < NN * DD; idx += blockDim.x) {
        int n = idx >> 6, d = idx & 63;
        R[n * 68 + d] = gr[idx];
    }
    __syncthreads();
    const float SC = 0.0625f;  // (1/sqrt(64)) / 2
    float* outm = g_att + (m * BB + b) * NN * NN + z * 32 * NN;
    for (int idx = tid; idx < 32 * NN; idx += blockDim.x) {
        int r = idx >> 6, c = idx & 63;          // r warp-uniform, c lane-spread
        const float4* L4 = (const float4*)(L + r * 68);
        const float4* R4 = (const float4*)(R + c * 68);
        float s = 0.f;
        #pragma unroll
        for (int d4 = 0; d4 < DD / 4; ++d4) {
            float4 lv = L4[d4], rv = R4[d4];
            s = fmaf(lv.x, rv.x, s); s = fmaf(lv.y, rv.y, s);
            s = fmaf(lv.z, rv.z, s); s = fmaf(lv.w, rv.w, s);
        }
        outm[idx] = SC * s;
    }
}

// ---------------------------------------------------------------------------
// Main: one block per (b,i). 256 thr: k = tid&63, jb = tid>>6 (16 j each).
// Proven R13 mainloop (launch_bounds(256,5), j-tile 2, split accumulators,
// one tanh.approx.f32 per element, analytic det^2 half-sum). Only change:
// the 4096-element smem fills are float4-vectorized (alkT pitch 68 = 17x16B
// keeps STS.128 aligned).
// ---------------------------------------------------------------------------
__global__ void __launch_bounds__(256, 5) main_kernel(const float* __restrict__ pc)
{
    extern __shared__ float sm[];
    float* bjl_s = sm;                     // 4096: ajl + aql[l]
    float* alkT  = sm + 4096;              // 64*68: akl[k][l] + aqk[k], pitch 68
    float* dispx = sm + 4096 + 4352;       // 64 each, 16B aligned
    float* dispy = dispx + 64;
    float* dispz = dispy + 64;
    float* aqj_s = dispz + 64;             // 64
    float* red   = aqj_s + 64;             // 8 partials (one per warp)

    const int tid = threadIdx.x;
    const int b = blockIdx.x >> 6, i = blockIdx.x & 63;
    const float* pcb = pc + b * NN * 3;
    const float pix = pcb[i * 3], piy = pcb[i * 3 + 1], piz = pcb[i * 3 + 2];

    for (int n = tid; n < NN; n += blockDim.x) {
        dispx[n] = pcb[n * 3 + 0] - pix;
        dispy[n] = pcb[n * 3 + 1] - piy;
        dispz[n] = pcb[n * 3 + 2] - piz;
    }

    const float* g_ajk = g_att + (0 * BB + b) * 4096;
    const float* g_ajl = g_att + (1 * BB + b) * 4096;
    const float* g_akl = g_att + (2 * BB + b) * 4096;   // [k][l]
    const float* aqj   = g_att + (3 * BB + b) * 4096 + i * NN;
    const float* aqk   = g_att + (4 * BB + b) * 4096 + i * NN;
    const float* aql   = g_att + (5 * BB + b) * 4096 + i * NN;

    {   // vectorized fills: 1024 float4 per array, 4 per thread
        const float4* ajl4 = (const float4*)g_ajl;
        const float4* akl4 = (const float4*)g_akl;
        const float4* aql4 = (const float4*)aql;
        #pragma unroll
        for (int p = 0; p < 4; ++p) {
            int idx4 = p * 256 + tid;
            int r = idx4 >> 4, c4 = idx4 & 15;
            float4 v = ajl4[idx4];
            float4 q = aql4[c4];
            v.x += q.x; v.y += q.y; v.z += q.z; v.w += q.w;
            ((float4*)bjl_s)[idx4] = v;
            float4 w = akl4[idx4];
            float ak = aqk[r];
            w.x += ak; w.y += ak; w.z += ak; w.w += ak;
            *(float4*)(alkT + r * 68 + c4 * 4) = w;
        }
    }
    for (int n = tid; n < NN; n += blockDim.x) aqj_s[n] = aqj[n];
    __syncthreads();

    const int k = tid & 63, jb = tid >> 6;
    const int j0base = jb * 16;
    const float dkx = dispx[k], dky = dispy[k], dkz = dispz[k];

    // ---- analytic det^2 half-sum for this thread's j subset ----
    float accD;
    {
        float qxx = 0, qxy = 0, qxz = 0, qyy = 0, qyz = 0, qzz = 0;
        #pragma unroll 4
        for (int jj = 0; jj < 16; ++jj) {
            float dx = dispx[j0base + jj], dy = dispy[j0base + jj], dz = dispz[j0base + jj];
            qxx = fmaf(dx, dx, qxx); qxy = fmaf(dx, dy, qxy); qxz = fmaf(dx, dz, qxz);
            qyy = fmaf(dy, dy, qyy); qyz = fmaf(dy, dz, qyz); qzz = fmaf(dz, dz, qzz);
        }
        const float* Mp = g_M + (b * NN + i) * 6;
        float Mxx = Mp[0], Mxy = Mp[1], Mxz = Mp[2], Myy = Mp[3], Myz = Mp[4], Mzz = Mp[5];
        // B = M * S, S = [dk]x (need all but B00)
        float B01 = fmaf(Mxz, dkx, -Mxx * dkz);
        float B02 = fmaf(Mxx, dky, -Mxy * dkx);
        float B10 = fmaf(Myy, dkz, -Myz * dky);
        float B11 = fmaf(Myz, dkx, -Mxy * dkz);
        float B12 = fmaf(Mxy, dky, -Myy * dkx);
        float B20 = fmaf(Myz, dkz, -Mzz * dky);
        float B21 = fmaf(Mzz, dkx, -Mxz * dkz);
        float B22 = fmaf(Mxz, dky, -Myz * dkx);
        // A = S^T * M * S (symmetric)
        float A00 = fmaf(dkz, B10, -dky * B20);
        float A01 = fmaf(dkz, B11, -dky * B21);
        float A02 = fmaf(dkz, B12, -dky * B22);
        float A11 = fmaf(dkx, B21, -dkz * B01);
        float A12 = fmaf(dkx, B22, -dkz * B02);
        float A22 = fmaf(dky, B02, -dkx * B12);
        accD = A00 * qxx + A11 * qyy + A22 * qzz
             + 2.f * (A01 * qxy + A02 * qxz + A12 * qyz);
    }

    U64 accT0 = 0, accT1 = 0;   // split accumulators: half the serial chain
    const float* alkrow = alkT + k * 68;
    const float* gajk_k = g_ajk + k;

    // prefetch c0 (ajk) for first j-tile
    float pf0 = gajk_k[(j0base + 0) * NN];
    float pf1 = gajk_k[(j0base + 1) * NN];

    for (int jt = 0; jt < 16; jt += 2) {
        const float c00 = pf0 + aqj_s[j0base + jt];
        const float c01 = pf1 + aqj_s[j0base + jt + 1];
        if (jt + 2 < 16) {   // prefetch next tile's ajk under this tile's math
            pf0 = gajk_k[(j0base + jt + 2) * NN];
            pf1 = gajk_k[(j0base + jt + 3) * NN];
        }
        U64 crx[2], cry[2], crz[2], c0p[2];
        c0p[0] = pk2(c00, c00); c0p[1] = pk2(c01, c01);
        #pragma unroll
        for (int u = 0; u < 2; ++u) {
            const int j = j0base + jt + u;
            const float djx = dispx[j], djy = dispy[j], djz = dispz[j];
            const float cx = fmaf(djy, dkz, -djz * dky);
            const float cy = fmaf(djz, dkx, -djx * dkz);
            const float cz = fmaf(djx, dky, -djy * dkx);
            crx[u] = pk2(cx, cx); cry[u] = pk2(cy, cy); crz[u] = pk2(cz, cz);
        }
        const float* bjlbase = bjl_s + (j0base + jt) * NN;

        #pragma unroll 1
        for (int l4 = 0; l4 < NN; l4 += 4) {
            // j-invariant loads, shared across the 2-j tile
            ulonglong2 ap = *(const ulonglong2*)(alkrow + l4);   // spread, 4 wf
            ulonglong2 xp = *(const ulonglong2*)(dispx + l4);    // broadcast
            ulonglong2 yp = *(const ulonglong2*)(dispy + l4);
            ulonglong2 zp = *(const ulonglong2*)(dispz + l4);
            #pragma unroll
            for (int u = 0; u < 2; ++u) {
                ulonglong2 bp = *(const ulonglong2*)(bjlbase + u * NN + l4); // broadcast
                U64 e0 = add2(add2(c0p[u], bp.x), ap.x);   // = E/2 for (l4, l4+1)
                U64 e1 = add2(add2(c0p[u], bp.y), ap.y);
                U64 d0 = fma2(crx[u], xp.x, fma2(cry[u], yp.x, mul2(crz[u], zp.x)));
                U64 d1 = fma2(crx[u], xp.y, fma2(cry[u], yp.y, mul2(crz[u], zp.y)));
                float ea, eb, ec, ed;
                upk2(e0, ea, eb); upk2(e1, ec, ed);
                U64 t0 = pk2(tanh_ap(ea), tanh_ap(eb));
                U64 t1 = pk2(tanh_ap(ec), tanh_ap(ed));
                if (u == 0) {
                    accT0 = fma2(t0, mul2(d0, d0), accT0);
                    accT0 = fma2(t1, mul2(d1, d1), accT0);
                } else {
                    accT1 = fma2(t0, mul2(d0, d0), accT1);
                    accT1 = fma2(t1, mul2(d1, d1), accT1);
                }
            }
        }
    }

    U64 accT = add2(accT0, accT1);
    float tlo, thi; upk2(accT, tlo, thi);
    float v = 0.5f * (tlo + thi) + 0.5f * accD;
    // warp reduce, then 8 partials through smem
    #pragma unroll
    for (int s = 16; s > 0; s >>= 1)
        v += __shfl_xor_sync(0xffffffffu, v, s);
    if ((tid & 31) == 0) red[tid >> 5] = v;
    __syncthreads();
    if (tid == 0) {
        float t = 0.f;
        #pragma unroll
        for (int w = 0; w < 8; ++w) t += red[w];
        g_agg[blockIdx.x] = t * (1.f / 262144.f);
    }
}

// ---------------------------------------------------------------------------
// Final: pool over anchors (parallel: 8 partial sums per batch), then
// 1->32->1 MLP with tanh-approx gelu on 32 threads. 256 threads total.
// ---------------------------------------------------------------------------
__global__ void final_kernel(const float* __restrict__ W1, const float* __restrict__ b1,
                             const float* __restrict__ W2, const float* __restrict__ b2,
                             float* __restrict__ out)
{
    __shared__ float part[256];
    const int tid = threadIdx.x;
    const int b = tid >> 3, s = tid & 7;
    const float* row = g_agg + b * NN + s * 8;
    float p = 0.f;
    #pragma unroll
    for (int q = 0; q < 8; ++q) p += row[q];
    part[tid] = p;
    __syncthreads();
    if (tid < BB) {
        float t = 0.f;
        #pragma unroll
        for (int q = 0; q < 8; ++q) t += part[tid * 8 + q];
        t *= (1.f / NN);
        float o = b2[0];
        for (int j = 0; j < 32; ++j) {
            float x = fmaf(t, W1[j], b1[j]);
            float inner = 0.7978845608028654f * (x + 0.044715f * x * x * x);
            float h = 0.5f * x * (1.f + tanhf(inner));
            o = fmaf(h, W2[j], o);
        }
        out[tid] = o;
    }
}

extern "C" void kernel_launch(void* const* d_in, const int* in_sizes, int n_in,
                              void* d_out, int out_size)
{
    const float* pc  = (const float*)d_in[0];
    const float* Wq  = (const float*)d_in[1];
    const float* bq  = (const float*)d_in[2];
    const float* Wk1 = (const float*)d_in[3];
    const float* bk1 = (const float*)d_in[4];
    const float* Wk2 = (const float*)d_in[5];
    const float* bk2 = (const float*)d_in[6];
    const float* Wk3 = (const float*)d_in[7];
    const float* bk3 = (const float*)d_in[8];
    const float* W1  = (const float*)d_in[9];
    const float* b1  = (const float*)d_in[10];
    const float* W2  = (const float*)d_in[11];
    const float* b2  = (const float*)d_in[12];
    float* out = (float*)d_out;

    // smem: 4096 + 4352 + 3*64 + 64 + 8 floats = 8712 floats = 34848 B
    const int MAIN_SMEM = (4096 + 4352 + 3 * 64 + 64 + 8) * (int)sizeof(float);
    cudaFuncSetAttribute(main_kernel, cudaFuncAttributeMaxDynamicSharedMemorySize, MAIN_SMEM);

    keys_kernel<<<dim3(4, 32), 256>>>(pc, Wq, bq, Wk1, bk1, Wk2, bk2, Wk3, bk3);
    att_kernel<<<dim3(6, 32, 2), 256>>>();
    main_kernel<<<BB * NN, 256, MAIN_SMEM>>>(pc);
    final_kernel<<<1, 256>>>(W1, b1, W2, b2, out);
}

// round 16
// speedup vs baseline: 1.2986x; 1.0021x over previous
#include <cuda_runtime.h>
#include <math.h>

#define BB 32
#define NN 64
#define DD 64
typedef unsigned long long U64;

// Scratch (no allocations allowed)
__device__ float g_att[6 * BB * NN * NN];    // 6 att matrices (pre-scaled by scale/2)
__device__ float g_M[BB * NN * 6];           // per (b,i): sum_l dl dl^T (6 unique)
__device__ float g_agg[BB * NN];
__device__ unsigned int g_ctr;               // last-block counter (self-resetting)

// ---- packed f32x2 helpers (FFMA2 only reachable via PTX) ----
__device__ __forceinline__ U64 pk2(float a, float b) {
    U64 r; asm("mov.b64 %0,{%1,%2};" : "=l"(r) : "f"(a), "f"(b)); return r;
}
__device__ __forceinline__ void upk2(U64 v, float& a, float& b) {
    asm("mov.b64 {%0,%1},%2;" : "=f"(a), "=f"(b) : "l"(v));
}
__device__ __forceinline__ U64 add2(U64 a, U64 b) {
    U64 d; asm("add.rn.f32x2 %0,%1,%2;" : "=l"(d) : "l"(a), "l"(b)); return d;
}
__device__ __forceinline__ U64 mul2(U64 a, U64 b) {
    U64 d; asm("mul.rn.f32x2 %0,%1,%2;" : "=l"(d) : "l"(a), "l"(b)); return d;
}
__device__ __forceinline__ U64 fma2(U64 a, U64 b, U64 c) {
    U64 d; asm("fma.rn.f32x2 %0,%1,%2,%3;" : "=l"(d) : "l"(a), "l"(b), "l"(c)); return d;
}
__device__ __forceinline__ float tanh_ap(float x) {
    float y; asm("tanh.approx.f32 %0,%1;" : "=f"(y) : "f"(x)); return y;
}

// ---------------------------------------------------------------------------
// Atts (keys fused): each block computes its two 3->64 key projections in
// smem directly from pc, then the 64x64 (z-split: 32x64) dot matrix,
// pre-scaled by scale/2 = 0.0625 (tanh half-arg).
// m: 0 ajk[j][k], 1 ajl[j][l], 2 akl[k][l] (k-major!), 3 aqj[i][j],
//    4 aqk[i][k], 5 aql[i][l].  grid (6, 32, 2), 256 thr.
// (m==0,z==0) blocks additionally compute g_M.
// ---------------------------------------------------------------------------
__global__ void att_kernel(const float* __restrict__ pc,
                           const float* __restrict__ Wq,  const float* __restrict__ bq,
                           const float* __restrict__ Wk1, const float* __restrict__ bk1,
                           const float* __restrict__ Wk2, const float* __restrict__ bk2,
                           const float* __restrict__ Wk3, const float* __restrict__ bk3)
{
    __shared__ float L[32 * 68];
    __shared__ float R[NN * 68];
    const int m = blockIdx.x, b = blockIdx.y, z = blockIdx.z, tid = threadIdx.x;
    const int lsel[6] = {1, 1, 2, 0, 0, 0};
    const int rsel[6] = {2, 3, 3, 1, 2, 3};
    const float* Ws[4] = {Wq, Wk1, Wk2, Wk3};
    const float* bs[4] = {bq, bk1, bk2, bk3};
    const float* Wl = Ws[lsel[m]]; const float* bl = bs[lsel[m]];
    const float* Wr = Ws[rsel[m]]; const float* br = bs[rsel[m]];
    const float* pcb = pc + b * NN * 3;

    // L: 32 rows (z*32 ..) of left key; R: all 64 rows of right key
    for (int idx = tid; idx < 32 * DD; idx += blockDim.x) {
        int n = idx >> 6, d = idx & 63;
        int g = z * 32 + n;
        float p0 = pcb[g * 3], p1 = pcb[g * 3 + 1], p2 = pcb[g * 3 + 2];
        L[n * 68 + d] = fmaf(p0, Wl[d], fmaf(p1, Wl[DD + d], fmaf(p2, Wl[2 * DD + d], bl[d])));
    }
    for (int idx = tid; idx < NN * DD; idx += blockDim.x) {
        int n = idx >> 6, d = idx & 63;
        float p0 = pcb[n * 3], p1 = pcb[n * 3 + 1], p2 = pcb[n * 3 + 2];
        R[n * 68 + d] = fmaf(p0, Wr[d], fmaf(p1, Wr[DD + d], fmaf(p2, Wr[2 * DD + d], br[d])));
    }
    __syncthreads();

    const float SC = 0.0625f;  // (1/sqrt(64)) / 2
    float* outm = g_att + (m * BB + b) * NN * NN + z * 32 * NN;
    for (int idx = tid; idx < 32 * NN; idx += blockDim.x) {
        int r = idx >> 6, c = idx & 63;          // r warp-uniform, c lane-spread
        const float4* L4 = (const float4*)(L + r * 68);
        const float4* R4 = (const float4*)(R + c * 68);
        float s = 0.f;
        #pragma unroll
        for (int d4 = 0; d4 < DD / 4; ++d4) {
            float4 lv = L4[d4], rv = R4[d4];
            s = fmaf(lv.x, rv.x, s); s = fmaf(lv.y, rv.y, s);
            s = fmaf(lv.z, rv.z, s); s = fmaf(lv.w, rv.w, s);
        }
        outm[idx] = SC * s;
    }

    if (m == 0 && z == 0 && tid < NN) {
        float pix = pcb[tid * 3], piy = pcb[tid * 3 + 1], piz = pcb[tid * 3 + 2];
        float xx = 0, xy = 0, xz = 0, yy = 0, yz = 0, zz = 0;
        #pragma unroll 4
        for (int l = 0; l < NN; ++l) {
            float dx = pcb[l * 3] - pix, dy = pcb[l * 3 + 1] - piy, dz = pcb[l * 3 + 2] - piz;
            xx = fmaf(dx, dx, xx); xy = fmaf(dx, dy, xy); xz = fmaf(dx, dz, xz);
            yy = fmaf(dy, dy, yy); yz = fmaf(dy, dz, yz); zz = fmaf(dz, dz, zz);
        }
        float* o = g_M + (b * NN + tid) * 6;
        o[0] = xx; o[1] = xy; o[2] = xz; o[3] = yy; o[4] = yz; o[5] = zz;
    }
}

// ---------------------------------------------------------------------------
// Main: one block per (b,i). 256 thr: k = tid&63, jb = tid>>6 (16 j each).
// Proven R13/R14 mainloop (launch_bounds(256,5), j-tile 2, split
// accumulators, one tanh.approx.f32 per element, analytic det^2 half-sum,
// float4 smem fills). New: threadfence-reduction tail — the last block to
// finish performs the anchor pooling + 1->32->1 gelu MLP (deterministic,
// fixed summation order; counter self-resets for graph replay).
// ---------------------------------------------------------------------------
__global__ void __launch_bounds__(256, 5) main_kernel(const float* __restrict__ pc,
                                                      const float* __restrict__ W1,
                                                      const float* __restrict__ b1,
                                                      const float* __restrict__ W2,
                                                      const float* __restrict__ b2,
                                                      float* __restrict__ out)
{
    extern __shared__ float sm[];
    float* bjl_s = sm;                     // 4096: ajl + aql[l]
    float* alkT  = sm + 4096;              // 64*68: akl[k][l] + aqk[k], pitch 68
    float* dispx = sm + 4096 + 4352;       // 64 each, 16B aligned
    float* dispy = dispx + 64;
    float* dispz = dispy + 64;
    float* aqj_s = dispz + 64;             // 64
    float* red   = aqj_s + 64;             // 8 partials (one per warp)
    __shared__ int s_last;

    const int tid = threadIdx.x;
    const int b = blockIdx.x >> 6, i = blockIdx.x & 63;
    const float* pcb = pc + b * NN * 3;
    const float pix = pcb[i * 3], piy = pcb[i * 3 + 1], piz = pcb[i * 3 + 2];

    for (int n = tid; n < NN; n += blockDim.x) {
        dispx[n] = pcb[n * 3 + 0] - pix;
        dispy[n] = pcb[n * 3 + 1] - piy;
        dispz[n] = pcb[n * 3 + 2] - piz;
    }

    const float* g_ajk = g_att + (0 * BB + b) * 4096;
    const float* g_ajl = g_att + (1 * BB + b) * 4096;
    const float* g_akl = g_att + (2 * BB + b) * 4096;   // [k][l]
    const float* aqj   = g_att + (3 * BB + b) * 4096 + i * NN;
    const float* aqk   = g_att + (4 * BB + b) * 4096 + i * NN;
    const float* aql   = g_att + (5 * BB + b) * 4096 + i * NN;

    {   // vectorized fills: 1024 float4 per array, 4 per thread
        const float4* ajl4 = (const float4*)g_ajl;
        const float4* akl4 = (const float4*)g_akl;
        const float4* aql4 = (const float4*)aql;
        #pragma unroll
        for (int p = 0; p < 4; ++p) {
            int idx4 = p * 256 + tid;
            int r = idx4 >> 4, c4 = idx4 & 15;
            float4 v = ajl4[idx4];
            float4 q = aql4[c4];
            v.x += q.x; v.y += q.y; v.z += q.z; v.w += q.w;
            ((float4*)bjl_s)[idx4] = v;
            float4 w = akl4[idx4];
            float ak = aqk[r];
            w.x += ak; w.y += ak; w.z += ak; w.w += ak;
            *(float4*)(alkT + r * 68 + c4 * 4) = w;
        }
    }
    for (int n = tid; n < NN; n += blockDim.x) aqj_s[n] = aqj[n];
    __syncthreads();

    const int k = tid & 63, jb = tid >> 6;
    const int j0base = jb * 16;
    const float dkx = dispx[k], dky = dispy[k], dkz = dispz[k];

    // ---- analytic det^2 half-sum for this thread's j subset ----
    float accD;
    {
        float qxx = 0, qxy = 0, qxz = 0, qyy = 0, qyz = 0, qzz = 0;
        #pragma unroll 4
        for (int jj = 0; jj < 16; ++jj) {
            float dx = dispx[j0base + jj], dy = dispy[j0base + jj], dz = dispz[j0base + jj];
            qxx = fmaf(dx, dx, qxx); qxy = fmaf(dx, dy, qxy); qxz = fmaf(dx, dz, qxz);
            qyy = fmaf(dy, dy, qyy); qyz = fmaf(dy, dz, qyz); qzz = fmaf(dz, dz, qzz);
        }
        const float* Mp = g_M + (b * NN + i) * 6;
        float Mxx = Mp[0], Mxy = Mp[1], Mxz = Mp[2], Myy = Mp[3], Myz = Mp[4], Mzz = Mp[5];
        // B = M * S, S = [dk]x (need all but B00)
        float B01 = fmaf(Mxz, dkx, -Mxx * dkz);
        float B02 = fmaf(Mxx, dky, -Mxy * dkx);
        float B10 = fmaf(Myy, dkz, -Myz * dky);
        float B11 = fmaf(Myz, dkx, -Mxy * dkz);
        float B12 = fmaf(Mxy, dky, -Myy * dkx);
        float B20 = fmaf(Myz, dkz, -Mzz * dky);
        float B21 = fmaf(Mzz, dkx, -Mxz * dkz);
        float B22 = fmaf(Mxz, dky, -Myz * dkx);
        // A = S^T * M * S (symmetric)
        float A00 = fmaf(dkz, B10, -dky * B20);
        float A01 = fmaf(dkz, B11, -dky * B21);
        float A02 = fmaf(dkz, B12, -dky * B22);
        float A11 = fmaf(dkx, B21, -dkz * B01);
        float A12 = fmaf(dkx, B22, -dkz * B02);
        float A22 = fmaf(dky, B02, -dkx * B12);
        accD = A00 * qxx + A11 * qyy + A22 * qzz
             + 2.f * (A01 * qxy + A02 * qxz + A12 * qyz);
    }

    U64 accT0 = 0, accT1 = 0;   // split accumulators: half the serial chain
    const float* alkrow = alkT + k * 68;
    const float* gajk_k = g_ajk + k;

    // prefetch c0 (ajk) for first j-tile
    float pf0 = gajk_k[(j0base + 0) * NN];
    float pf1 = gajk_k[(j0base + 1) * NN];

    for (int jt = 0; jt < 16; jt += 2) {
        const float c00 = pf0 + aqj_s[j0base + jt];
        const float c01 = pf1 + aqj_s[j0base + jt + 1];
        if (jt + 2 < 16) {   // prefetch next tile's ajk under this tile's math
            pf0 = gajk_k[(j0base + jt + 2) * NN];
            pf1 = gajk_k[(j0base + jt + 3) * NN];
        }
        U64 crx[2], cry[2], crz[2], c0p[2];
        c0p[0] = pk2(c00, c00); c0p[1] = pk2(c01, c01);
        #pragma unroll
        for (int u = 0; u < 2; ++u) {
            const int j = j0base + jt + u;
            const float djx = dispx[j], djy = dispy[j], djz = dispz[j];
            const float cx = fmaf(djy, dkz, -djz * dky);
            const float cy = fmaf(djz, dkx, -djx * dkz);
            const float cz = fmaf(djx, dky, -djy * dkx);
            crx[u] = pk2(cx, cx); cry[u] = pk2(cy, cy); crz[u] = pk2(cz, cz);
        }
        const float* bjlbase = bjl_s + (j0base + jt) * NN;

        #pragma unroll 1
        for (int l4 = 0; l4 < NN; l4 += 4) {
            // j-invariant loads, shared across the 2-j tile
            ulonglong2 ap = *(const ulonglong2*)(alkrow + l4);   // spread, 4 wf
            ulonglong2 xp = *(const ulonglong2*)(dispx + l4);    // broadcast
            ulonglong2 yp = *(const ulonglong2*)(dispy + l4);
            ulonglong2 zp = *(const ulonglong2*)(dispz + l4);
            #pragma unroll
            for (int u = 0; u < 2; ++u) {
                ulonglong2 bp = *(const ulonglong2*)(bjlbase + u * NN + l4); // broadcast
                U64 e0 = add2(add2(c0p[u], bp.x), ap.x);   // = E/2 for (l4, l4+1)
                U64 e1 = add2(add2(c0p[u], bp.y), ap.y);
                U64 d0 = fma2(crx[u], xp.x, fma2(cry[u], yp.x, mul2(crz[u], zp.x)));
                U64 d1 = fma2(crx[u], xp.y, fma2(cry[u], yp.y, mul2(crz[u], zp.y)));
                float ea, eb, ec, ed;
                upk2(e0, ea, eb); upk2(e1, ec, ed);
                U64 t0 = pk2(tanh_ap(ea), tanh_ap(eb));
                U64 t1 = pk2(tanh_ap(ec), tanh_ap(ed));
                if (u == 0) {
                    accT0 = fma2(t0, mul2(d0, d0), accT0);
                    accT0 = fma2(t1, mul2(d1, d1), accT0);
                } else {
                    accT1 = fma2(t0, mul2(d0, d0), accT1);
                    accT1 = fma2(t1, mul2(d1, d1), accT1);
                }
            }
        }
    }

    U64 accT = add2(accT0, accT1);
    float tlo, thi; upk2(accT, tlo, thi);
    float v = 0.5f * (tlo + thi) + 0.5f * accD;
    // warp reduce, then 8 partials through smem
    #pragma unroll
    for (int s = 16; s > 0; s >>= 1)
        v += __shfl_xor_sync(0xffffffffu, v, s);
    if ((tid & 31) == 0) red[tid >> 5] = v;
    __syncthreads();
    if (tid == 0) {
        float t = 0.f;
        #pragma unroll
        for (int w = 0; w < 8; ++w) t += red[w];
        g_agg[blockIdx.x] = t * (1.f / 262144.f);
    }

    // ---- last-block tail: anchor pooling + 1->32->1 gelu MLP ----
    __threadfence();
    if (tid == 0) {
        unsigned int c = atomicAdd(&g_ctr, 1u);
        s_last = (c == (unsigned)(BB * NN - 1));
    }
    __syncthreads();
    if (s_last) {
        float* part = bjl_s;   // reuse smem
        const int bb = tid >> 3, ss = tid & 7;
        const float* row = g_agg + bb * NN + ss * 8;
        float p = 0.f;
        #pragma unroll
        for (int q = 0; q < 8; ++q) p += row[q];
        part[tid] = p;
        __syncthreads();
        if (tid < BB) {
            float t = 0.f;
            #pragma unroll
            for (int q = 0; q < 8; ++q) t += part[tid * 8 + q];
            t *= (1.f / NN);
            float o = b2[0];
            for (int j = 0; j < 32; ++j) {
                float x = fmaf(t, W1[j], b1[j]);
                float inner = 0.7978845608028654f * (x + 0.044715f * x * x * x);
                float h = 0.5f * x * (1.f + tanhf(inner));
                o = fmaf(h, W2[j], o);
            }
            out[tid] = o;
        }
        if (tid == 0) g_ctr = 0;   // reset for next graph replay
    }
}

extern "C" void kernel_launch(void* const* d_in, const int* in_sizes, int n_in,
                              void* d_out, int out_size)
{
    const float* pc  = (const float*)d_in[0];
    const float* Wq  = (const float*)d_in[1];
    const float* bq  = (const float*)d_in[2];
    const float* Wk1 = (const float*)d_in[3];
    const float* bk1 = (const float*)d_in[4];
    const float* Wk2 = (const float*)d_in[5];
    const float* bk2 = (const float*)d_in[6];
    const float* Wk3 = (const float*)d_in[7];
    const float* bk3 = (const float*)d_in[8];
    const float* W1  = (const float*)d_in[9];
    const float* b1  = (const float*)d_in[10];
    const float* W2  = (const float*)d_in[11];
    const float* b2  = (const float*)d_in[12];
    float* out = (float*)d_out;

    // smem: 4096 + 4352 + 3*64 + 64 + 8 floats = 8712 floats = 34848 B
    const int MAIN_SMEM = (4096 + 4352 + 3 * 64 + 64 + 8) * (int)sizeof(float);
    cudaFuncSetAttribute(main_kernel, cudaFuncAttributeMaxDynamicSharedMemorySize, MAIN_SMEM);

    att_kernel<<<dim3(6, 32, 2), 256>>>(pc, Wq, bq, Wk1, bk1, Wk2, bk2, Wk3, bk3);
    main_kernel<<<BB * NN, 256, MAIN_SMEM>>>(pc, W1, b1, W2, b2, out);
}